// round 5
// baseline (speedup 1.0000x reference)
#include <cuda_runtime.h>
#include <cuda_bf16.h>
#include <math.h>
#include <cstdint>

// ---------------------------------------------------------------------------
// Problem constants
// ---------------------------------------------------------------------------
#define BB 16
#define TT 7
#define NN 2048
#define DD 128
#define M1 (BB*TT*NN)   /* 229376 */
#define M0 (BB*NN)      /* 32768  */

// ---------------------------------------------------------------------------
// mma.sync / ldmatrix helpers (generic sm_80+, works on compute_100)
// ---------------------------------------------------------------------------
__device__ __forceinline__ uint32_t smem_u32(const void* p) {
    uint32_t a;
    asm("{ .reg .u64 t; cvta.to.shared.u64 t, %1; cvt.u32.u64 %0, t; }" : "=r"(a) : "l"(p));
    return a;
}

#define LDM4(r, a) \
    asm volatile("ldmatrix.sync.aligned.m8n8.x4.shared.b16 {%0,%1,%2,%3}, [%4];" \
        : "=r"((r)[0]), "=r"((r)[1]), "=r"((r)[2]), "=r"((r)[3]) : "r"(a))

#define MMA16(c, a, b0_, b1_) \
    asm volatile("mma.sync.aligned.m16n8k16.row.col.f32.bf16.bf16.f32 " \
        "{%0,%1,%2,%3},{%4,%5,%6,%7},{%8,%9},{%0,%1,%2,%3};" \
        : "+f"((c)[0]), "+f"((c)[1]), "+f"((c)[2]), "+f"((c)[3]) \
        : "r"((a)[0]), "r"((a)[1]), "r"((a)[2]), "r"((a)[3]), "r"(b0_), "r"(b1_))

// ---------------------------------------------------------------------------
// Device scratch
// ---------------------------------------------------------------------------
__device__ __nv_bfloat16 g_Wb1[6 * 16384];   // QKV X-part: [jt*2+hl][n][k]
__device__ __nv_bfloat16 g_Wb2[6 * 16384];   // QKV STE-part
__device__ __nv_bfloat16 g_Wbo[2 * 16384];   // O weights
__device__ float g_bias[384];
__device__ float g_ste[(size_t)M0 * 384];
__device__ float g_y[(size_t)M1 * 384];
__device__ float g_attout[(size_t)M1 * 128];
__device__ float g_opre[(size_t)M1 * 128];
__device__ float g_stats[1024];
__device__ float g_bnscale[512];
__device__ float g_bnshift[512];

__device__ __forceinline__ float gelu_f(float x) {
    return 0.5f * x * (1.0f + erff(x * 0.70710678118654752f));
}

// ---------------------------------------------------------------------------
// Utility kernels
// ---------------------------------------------------------------------------
__global__ void zero_stats_kernel() { g_stats[threadIdx.x] = 0.0f; }

__global__ void pack_qkv_kernel(const float* __restrict__ wq, const float* __restrict__ bq,
                                const float* __restrict__ wk, const float* __restrict__ bk,
                                const float* __restrict__ wv, const float* __restrict__ bv) {
    int idx = blockIdx.x * blockDim.x + threadIdx.x;
    if (idx >= 3 * 128 * 128) return;
    int jt = idx >> 14;
    int n  = (idx >> 7) & 127;
    int k  = idx & 127;
    const float* w = (jt == 0) ? wq : (jt == 1) ? wk : wv;
    float v1 = w[k * 128 + n];
    float v2 = w[(k + 128) * 128 + n];
    __nv_bfloat16 h1 = __float2bfloat16(v1);
    __nv_bfloat16 h2 = __float2bfloat16(v2);
    g_Wb1[(jt * 2 + 0) * 16384 + n * 128 + k] = h1;
    g_Wb1[(jt * 2 + 1) * 16384 + n * 128 + k] = __float2bfloat16(v1 - __bfloat162float(h1));
    g_Wb2[(jt * 2 + 0) * 16384 + n * 128 + k] = h2;
    g_Wb2[(jt * 2 + 1) * 16384 + n * 128 + k] = __float2bfloat16(v2 - __bfloat162float(h2));
    if (k == 0) {
        const float* bb = (jt == 0) ? bq : (jt == 1) ? bk : bv;
        g_bias[jt * 128 + n] = bb[n];
    }
}

__global__ void pack_wo_kernel(const float* __restrict__ wo) {
    int idx = blockIdx.x * blockDim.x + threadIdx.x;
    if (idx >= 16384) return;
    int n = idx >> 7, k = idx & 127;
    float v = wo[k * 128 + n];
    __nv_bfloat16 h = __float2bfloat16(v);
    g_Wbo[n * 128 + k] = h;
    g_Wbo[16384 + n * 128 + k] = __float2bfloat16(v - __bfloat162float(h));
}

// ---------------------------------------------------------------------------
// bf16 split-3 tensor-core GEMM via mma.sync, 512 threads (16 warps, 4x4).
//   C[m0:m0+128, 0:NJT*128] = A[m0:m0+128, 0:128] @ Bp^T (+bias)(+ste)(+stats)
//   Warp tile 32x32, mma m16n8k16, 3 split terms (hh, hl, lh).
// SMEM: A_hi 0..34816, A_lo ..69632, B_hi ..104448, B_lo ..139264, stats +1024
// ---------------------------------------------------------------------------
static constexpr int HG_SMEM = 139264 + 1024;

template<int NJT, bool STEADD, bool STATS, bool BIASF, bool QKVMAP>
__global__ void __launch_bounds__(512, 1)
hgemm_kernel(const float* __restrict__ A, const __nv_bfloat16* __restrict__ Bp,
             const float* __restrict__ bias, const float* __restrict__ steg,
             float* __restrict__ C, float* __restrict__ stats, int statsOff)
{
    constexpr int NC = NJT * 128;
    constexpr int A_LO = 34816, B_HI = 69632, B_LO = 104448;
    constexpr int ST_OFF = 139264;

    extern __shared__ char sm[];
    const uint32_t sb = smem_u32(sm);

    const int tid  = threadIdx.x;
    const int lane = tid & 31;
    const int wid  = tid >> 5;
    const int wm   = wid >> 2;      // 0..3
    const int wn   = wid & 3;       // 0..3

    int m0, sterow0 = 0;
    if (QKVMAP) {
        int bx = blockIdx.x;
        int t = bx % 7, u = bx / 7;
        int nblk = u & 15, b = u >> 4;
        m0 = (b * 7 + t) * NN + nblk * 128;
        sterow0 = b * NN + nblk * 128;
    } else {
        m0 = blockIdx.x * 128;
    }

    // ---- load A tile, split fp32 -> bf16 hi/lo into padded smem (stride 272B) ----
    {
        const float* Ag = A + (size_t)m0 * 128;
        #pragma unroll
        for (int i = 0; i < 8; i++) {
            int f  = tid + i * 512;       // 0..4095 float4s
            int r  = f >> 5;
            int c4 = (f & 31) << 2;
            float4 v = *(const float4*)(Ag + (size_t)r * 128 + c4);
            __nv_bfloat16 hx = __float2bfloat16(v.x);
            __nv_bfloat16 hy = __float2bfloat16(v.y);
            __nv_bfloat16 hz = __float2bfloat16(v.z);
            __nv_bfloat16 hw = __float2bfloat16(v.w);
            __nv_bfloat162 hp0; hp0.x = hx; hp0.y = hy;
            __nv_bfloat162 hp1; hp1.x = hz; hp1.y = hw;
            uint2 hv; hv.x = *(uint32_t*)&hp0; hv.y = *(uint32_t*)&hp1;
            __nv_bfloat162 lp0, lp1;
            lp0.x = __float2bfloat16(v.x - __bfloat162float(hx));
            lp0.y = __float2bfloat16(v.y - __bfloat162float(hy));
            lp1.x = __float2bfloat16(v.z - __bfloat162float(hz));
            lp1.y = __float2bfloat16(v.w - __bfloat162float(hw));
            uint2 lv; lv.x = *(uint32_t*)&lp0; lv.y = *(uint32_t*)&lp1;
            *(uint2*)(sm + r * 272 + c4 * 2)        = hv;
            *(uint2*)(sm + A_LO + r * 272 + c4 * 2) = lv;
        }
    }

    const int gid = lane >> 2, tig = lane & 3;
    const uint32_t aBase = sb + (wm * 32 + (lane & 15)) * 272 + ((lane >> 4) & 1) * 16;
    const uint32_t bBase = sb + B_HI + (wn * 32 + (lane & 7) + ((lane >> 4) << 3)) * 272
                              + ((lane >> 3) & 1) * 16;

    #pragma unroll 1
    for (int jt = 0; jt < NJT; jt++) {
        __syncthreads();   // previous epilogue done before overwriting B/stats

        // ---- load B j-tile (hi+lo) into padded smem ----
        {
            const __nv_bfloat16* Bg = Bp + (size_t)jt * 2 * 16384;
            #pragma unroll
            for (int i = 0; i < 8; i++) {
                int f  = tid + i * 512;      // 0..4095 uint4s
                int hl = f >> 11;
                int g  = f & 2047;
                int r  = g >> 4;
                int ch = g & 15;
                uint4 val = ((const uint4*)(Bg + hl * 16384))[r * 16 + ch];
                *(uint4*)(sm + B_HI + hl * 34816 + r * 272 + ch * 16) = val;
            }
        }
        if (STATS && tid < 128) {
            ((float*)(sm + ST_OFF))[tid] = 0.0f;
            ((float*)(sm + ST_OFF))[tid + 128] = 0.0f;
        }
        __syncthreads();

        // ---- mainloop: K=128 in 8 steps of k16, 3 split terms ----
        float acc[2][4][4];
        #pragma unroll
        for (int i = 0; i < 2; i++)
            #pragma unroll
            for (int j = 0; j < 4; j++)
                #pragma unroll
                for (int q = 0; q < 4; q++) acc[i][j][q] = 0.0f;

        #pragma unroll
        for (int kb = 0; kb < 8; kb++) {
            const int kby = kb * 32;
            uint32_t ah[2][4], al[2][4], bh[2][4], bl[2][4];
            #pragma unroll
            for (int mf = 0; mf < 2; mf++) LDM4(ah[mf], aBase + mf * 4352 + kby);
            #pragma unroll
            for (int mf = 0; mf < 2; mf++) LDM4(al[mf], aBase + A_LO + mf * 4352 + kby);
            #pragma unroll
            for (int g2 = 0; g2 < 2; g2++) LDM4(bh[g2], bBase + g2 * 4352 + kby);
            #pragma unroll
            for (int g2 = 0; g2 < 2; g2++) LDM4(bl[g2], bBase + 34816 + g2 * 4352 + kby);

            #pragma unroll
            for (int mf = 0; mf < 2; mf++)
                #pragma unroll
                for (int ng = 0; ng < 4; ng++) {
                    int g = ng >> 1, o = (ng & 1) * 2;
                    MMA16(acc[mf][ng], ah[mf], bh[g][o], bh[g][o + 1]);
                }
            #pragma unroll
            for (int mf = 0; mf < 2; mf++)
                #pragma unroll
                for (int ng = 0; ng < 4; ng++) {
                    int g = ng >> 1, o = (ng & 1) * 2;
                    MMA16(acc[mf][ng], ah[mf], bl[g][o], bl[g][o + 1]);
                }
            #pragma unroll
            for (int mf = 0; mf < 2; mf++)
                #pragma unroll
                for (int ng = 0; ng < 4; ng++) {
                    int g = ng >> 1, o = (ng & 1) * 2;
                    MMA16(acc[mf][ng], al[mf], bh[g][o], bh[g][o + 1]);
                }
        }

        // ---- epilogue ----
        float csum[8], csq[8];
        #pragma unroll
        for (int i = 0; i < 8; i++) { csum[i] = 0.0f; csq[i] = 0.0f; }

        float2 bb[4];
        #pragma unroll
        for (int ng = 0; ng < 4; ng++) {
            if (BIASF) bb[ng] = *(const float2*)(bias + jt * 128 + wn * 32 + ng * 8 + tig * 2);
            else       bb[ng] = make_float2(0.0f, 0.0f);
        }

        #pragma unroll
        for (int mf = 0; mf < 2; mf++) {
            int mloc0 = wm * 32 + mf * 16 + gid;
            #pragma unroll
            for (int ng = 0; ng < 4; ng++) {
                int nloc = wn * 32 + ng * 8 + tig * 2;
                int jcol = jt * 128 + nloc;
                #pragma unroll
                for (int h = 0; h < 2; h++) {
                    int mloc = mloc0 + h * 8;
                    float v0 = acc[mf][ng][h * 2 + 0] + bb[ng].x;
                    float v1 = acc[mf][ng][h * 2 + 1] + bb[ng].y;
                    if (STEADD) {
                        float2 ss = *(const float2*)(steg + (size_t)(sterow0 + mloc) * 384 + jcol);
                        v0 += ss.x; v1 += ss.y;
                    }
                    *(float2*)(C + (size_t)(m0 + mloc) * NC + jcol) = make_float2(v0, v1);
                    if (STATS) {
                        csum[ng * 2 + 0] += v0; csq[ng * 2 + 0] += v0 * v0;
                        csum[ng * 2 + 1] += v1; csq[ng * 2 + 1] += v1 * v1;
                    }
                }
            }
        }

        if (STATS) {
            float* ssum = (float*)(sm + ST_OFF);
            float* ssq  = ssum + 128;
            #pragma unroll
            for (int ng = 0; ng < 4; ng++) {
                #pragma unroll
                for (int h2 = 0; h2 < 2; h2++) {
                    int nl = wn * 32 + ng * 8 + tig * 2 + h2;
                    atomicAdd(&ssum[nl], csum[ng * 2 + h2]);
                    atomicAdd(&ssq[nl],  csq[ng * 2 + h2]);
                }
            }
            __syncthreads();
            if (tid < 128) {
                atomicAdd(&stats[statsOff + jt * 128 + tid],       ssum[tid]);
                atomicAdd(&stats[512 + statsOff + jt * 128 + tid], ssq[tid]);
            }
        }
    }
}

// ---------------------------------------------------------------------------
// BN affine params
// ---------------------------------------------------------------------------
__global__ void bn_params_kernel(const float* __restrict__ stats, int off,
                                 const float* __restrict__ gamma, const float* __restrict__ beta,
                                 float* __restrict__ scale, float* __restrict__ shift,
                                 int outOff, float invM)
{
    int c = threadIdx.x;
    float s  = stats[off + c];
    float sq = stats[512 + off + c];
    float mu  = s * invM;
    float var = sq * invM - mu * mu;
    float rs  = rsqrtf(var + 1e-5f);
    float sc  = gamma[c] * rs;
    scale[outOff + c] = sc;
    shift[outOff + c] = beta[c] - mu * sc;
}

// ---------------------------------------------------------------------------
// Fused BN+GELU(q,k,v) + 16-head dim-8 attention over T=7, per (b,n)
// ---------------------------------------------------------------------------
__global__ void __launch_bounds__(128)
attn_kernel(const float* __restrict__ y, const float* __restrict__ scale,
            const float* __restrict__ shift, float* __restrict__ att_out)
{
    __shared__ float qkv[7][384];
    __shared__ float obuf[7][128];

    int bn  = blockIdx.x;
    int b   = bn >> 11;
    int n   = bn & (NN - 1);
    int tid = threadIdx.x;

    #pragma unroll
    for (int t = 0; t < 7; t++) {
        const float* row = y + (size_t)((b * 7 + t) * NN + n) * 384;
        #pragma unroll
        for (int it = 0; it < 3; it++) {
            int idx = tid + it * 128;
            float v = row[idx] * scale[idx] + shift[idx];
            qkv[t][idx] = gelu_f(v);
        }
    }
    __syncthreads();

    if (tid < 112) {
        int h = tid / 7;
        int t = tid - h * 7;
        int off = h * 8;
        float s[7], mx = -1e30f;
        #pragma unroll
        for (int j = 0; j < 7; j++) {
            float dsum = 0.0f;
            #pragma unroll
            for (int c = 0; c < 8; c++) dsum += qkv[t][off + c] * qkv[j][128 + off + c];
            s[j] = dsum * 0.25f;
            mx = fmaxf(mx, s[j]);
        }
        float ssum = 0.0f;
        #pragma unroll
        for (int j = 0; j < 7; j++) { s[j] = __expf(s[j] - mx); ssum += s[j]; }
        float inv = 1.0f / ssum;
        float o[8];
        #pragma unroll
        for (int c = 0; c < 8; c++) o[c] = 0.0f;
        #pragma unroll
        for (int j = 0; j < 7; j++) {
            float p = s[j] * inv;
            #pragma unroll
            for (int c = 0; c < 8; c++) o[c] += p * qkv[j][256 + off + c];
        }
        #pragma unroll
        for (int c = 0; c < 8; c++) obuf[t][off + c] = o[c];
    }
    __syncthreads();

    #pragma unroll
    for (int t = 0; t < 7; t++)
        att_out[(size_t)((b * 7 + t) * NN + n) * 128 + tid] = obuf[t][tid];
}

// ---------------------------------------------------------------------------
// Final: BN+GELU(o) fused with Linear(7->1) over time
// ---------------------------------------------------------------------------
__global__ void final_kernel(const float* __restrict__ opre, const float* __restrict__ lw,
                             const float* __restrict__ lb, const float* __restrict__ scale,
                             const float* __restrict__ shift, float* __restrict__ out)
{
    int idx = blockIdx.x * blockDim.x + threadIdx.x;
    if (idx >= BB * NN * DD) return;
    int d = idx & 127;
    int n = (idx >> 7) & (NN - 1);
    int b = idx >> 18;
    float sc = scale[d], sh = shift[d];
    float acc = lb[0];
    #pragma unroll
    for (int t = 0; t < 7; t++) {
        float v = opre[(size_t)((b * 7 + t) * NN + n) * 128 + d];
        acc += gelu_f(v * sc + sh) * lw[t];
    }
    out[idx] = acc;
}

// ---------------------------------------------------------------------------
// Launcher
// ---------------------------------------------------------------------------
extern "C" void kernel_launch(void* const* d_in, const int* in_sizes, int n_in,
                              void* d_out, int out_size)
{
    const float* X   = (const float*)d_in[0];
    const float* STE = (const float*)d_in[1];
    const float* wq  = (const float*)d_in[2];
    const float* bq  = (const float*)d_in[3];
    const float* gq  = (const float*)d_in[4];
    const float* btq = (const float*)d_in[5];
    const float* wk  = (const float*)d_in[6];
    const float* bk  = (const float*)d_in[7];
    const float* gk  = (const float*)d_in[8];
    const float* btk = (const float*)d_in[9];
    const float* wv  = (const float*)d_in[10];
    const float* bv  = (const float*)d_in[11];
    const float* gv  = (const float*)d_in[12];
    const float* btv = (const float*)d_in[13];
    const float* wo  = (const float*)d_in[14];
    const float* bo  = (const float*)d_in[15];
    const float* go  = (const float*)d_in[16];
    const float* bto = (const float*)d_in[17];
    const float* lw  = (const float*)d_in[18];
    const float* lb  = (const float*)d_in[19];
    float* out = (float*)d_out;

    float *pBias, *pSte, *pY, *pAtt, *pOpre, *pStats, *pScale, *pShift;
    __nv_bfloat16 *pWb1, *pWb2, *pWbo;
    cudaGetSymbolAddress((void**)&pWb1,   g_Wb1);
    cudaGetSymbolAddress((void**)&pWb2,   g_Wb2);
    cudaGetSymbolAddress((void**)&pWbo,   g_Wbo);
    cudaGetSymbolAddress((void**)&pBias,  g_bias);
    cudaGetSymbolAddress((void**)&pSte,   g_ste);
    cudaGetSymbolAddress((void**)&pY,     g_y);
    cudaGetSymbolAddress((void**)&pAtt,   g_attout);
    cudaGetSymbolAddress((void**)&pOpre,  g_opre);
    cudaGetSymbolAddress((void**)&pStats, g_stats);
    cudaGetSymbolAddress((void**)&pScale, g_bnscale);
    cudaGetSymbolAddress((void**)&pShift, g_bnshift);

    cudaFuncSetAttribute((const void*)hgemm_kernel<3, false, false, true,  false>,
                         cudaFuncAttributeMaxDynamicSharedMemorySize, HG_SMEM);
    cudaFuncSetAttribute((const void*)hgemm_kernel<3, true,  true,  false, true>,
                         cudaFuncAttributeMaxDynamicSharedMemorySize, HG_SMEM);
    cudaFuncSetAttribute((const void*)hgemm_kernel<1, false, true,  true,  false>,
                         cudaFuncAttributeMaxDynamicSharedMemorySize, HG_SMEM);

    const float invM = 1.0f / (float)M1;

    zero_stats_kernel<<<1, 1024>>>();
    pack_qkv_kernel<<<(3 * 128 * 128 + 255) / 256, 256>>>(wq, bq, wk, bk, wv, bv);
    pack_wo_kernel<<<64, 256>>>(wo);

    // STE part of QKV FC: [32768,128] @ W2 + bias -> g_ste
    hgemm_kernel<3, false, false, true, false><<<M0 / 128, 512, HG_SMEM>>>(
        STE, pWb2, pBias, nullptr, pSte, nullptr, 0);

    // X part + STE add + stats: [229376,128] @ W1 -> g_y
    hgemm_kernel<3, true, true, false, true><<<M1 / 128, 512, HG_SMEM>>>(
        X, pWb1, nullptr, pSte, pY, pStats, 0);

    bn_params_kernel<<<1, 128>>>(pStats,   0, gq, btq, pScale, pShift,   0, invM);
    bn_params_kernel<<<1, 128>>>(pStats, 128, gk, btk, pScale, pShift, 128, invM);
    bn_params_kernel<<<1, 128>>>(pStats, 256, gv, btv, pScale, pShift, 256, invM);

    attn_kernel<<<M0, 128>>>(pY, pScale, pShift, pAtt);

    // O FC: [229376,128] @ wo + bias + stats -> g_opre
    hgemm_kernel<1, false, true, true, false><<<M1 / 128, 512, HG_SMEM>>>(
        pAtt, pWbo, bo, nullptr, pOpre, pStats, 384);

    bn_params_kernel<<<1, 128>>>(pStats, 384, go, bto, pScale, pShift, 384, invM);

    final_kernel<<<(BB * NN * DD + 255) / 256, 256>>>(pOpre, lw, lb, pScale + 384, pShift + 384, out);
}

// round 7
// speedup vs baseline: 1.0628x; 1.0628x over previous
#include <cuda_runtime.h>
#include <cuda_bf16.h>
#include <math.h>
#include <cstdint>

// ---------------------------------------------------------------------------
// Problem constants
// ---------------------------------------------------------------------------
#define BB 16
#define TT 7
#define NN 2048
#define DD 128
#define M1 (BB*TT*NN)   /* 229376 */
#define M0 (BB*NN)      /* 32768  */

// ---------------------------------------------------------------------------
// mma.sync / ldmatrix / cp.async helpers (generic sm_80+, works on compute_100)
// ---------------------------------------------------------------------------
__device__ __forceinline__ uint32_t smem_u32(const void* p) {
    uint32_t a;
    asm("{ .reg .u64 t; cvta.to.shared.u64 t, %1; cvt.u32.u64 %0, t; }" : "=r"(a) : "l"(p));
    return a;
}

#define LDM4(r, a) \
    asm volatile("ldmatrix.sync.aligned.m8n8.x4.shared.b16 {%0,%1,%2,%3}, [%4];" \
        : "=r"((r)[0]), "=r"((r)[1]), "=r"((r)[2]), "=r"((r)[3]) : "r"(a))

#define MMA16(c, a, b0_, b1_) \
    asm volatile("mma.sync.aligned.m16n8k16.row.col.f32.bf16.bf16.f32 " \
        "{%0,%1,%2,%3},{%4,%5,%6,%7},{%8,%9},{%0,%1,%2,%3};" \
        : "+f"((c)[0]), "+f"((c)[1]), "+f"((c)[2]), "+f"((c)[3]) \
        : "r"((a)[0]), "r"((a)[1]), "r"((a)[2]), "r"((a)[3]), "r"(b0_), "r"(b1_))

#define CP_ASYNC16(dst, src) \
    asm volatile("cp.async.ca.shared.global [%0], [%1], 16;" :: "r"(dst), "l"(src) : "memory")
#define CP_COMMIT() asm volatile("cp.async.commit_group;" ::: "memory")
#define CP_WAIT0()  asm volatile("cp.async.wait_group 0;" ::: "memory")
#define CP_WAIT1()  asm volatile("cp.async.wait_group 1;" ::: "memory")

// ---------------------------------------------------------------------------
// Device scratch
// ---------------------------------------------------------------------------
__device__ __nv_bfloat16 g_Wb1[6 * 16384];   // QKV X-part: [jt*2+hl][n][k]
__device__ __nv_bfloat16 g_Wb2[6 * 16384];   // QKV STE-part
__device__ __nv_bfloat16 g_Wbo[2 * 16384];   // O weights
__device__ float g_bias[384];
__device__ float g_ste[(size_t)M0 * 384];
__device__ float g_y[(size_t)M1 * 384];
__device__ float g_attout[(size_t)M1 * 128];
__device__ float g_opre[(size_t)M1 * 128];
__device__ float g_stats[1024];
__device__ float g_bnscale[512];
__device__ float g_bnshift[512];

__device__ __forceinline__ float gelu_f(float x) {
    return 0.5f * x * (1.0f + erff(x * 0.70710678118654752f));
}

// ---------------------------------------------------------------------------
// Utility kernels
// ---------------------------------------------------------------------------
__global__ void zero_stats_kernel() { g_stats[threadIdx.x] = 0.0f; }

__global__ void pack_qkv_kernel(const float* __restrict__ wq, const float* __restrict__ bq,
                                const float* __restrict__ wk, const float* __restrict__ bk,
                                const float* __restrict__ wv, const float* __restrict__ bv) {
    int idx = blockIdx.x * blockDim.x + threadIdx.x;
    if (idx >= 3 * 128 * 128) return;
    int jt = idx >> 14;
    int n  = (idx >> 7) & 127;
    int k  = idx & 127;
    const float* w = (jt == 0) ? wq : (jt == 1) ? wk : wv;
    float v1 = w[k * 128 + n];
    float v2 = w[(k + 128) * 128 + n];
    __nv_bfloat16 h1 = __float2bfloat16(v1);
    __nv_bfloat16 h2 = __float2bfloat16(v2);
    g_Wb1[(jt * 2 + 0) * 16384 + n * 128 + k] = h1;
    g_Wb1[(jt * 2 + 1) * 16384 + n * 128 + k] = __float2bfloat16(v1 - __bfloat162float(h1));
    g_Wb2[(jt * 2 + 0) * 16384 + n * 128 + k] = h2;
    g_Wb2[(jt * 2 + 1) * 16384 + n * 128 + k] = __float2bfloat16(v2 - __bfloat162float(h2));
    if (k == 0) {
        const float* bb = (jt == 0) ? bq : (jt == 1) ? bk : bv;
        g_bias[jt * 128 + n] = bb[n];
    }
}

__global__ void pack_wo_kernel(const float* __restrict__ wo) {
    int idx = blockIdx.x * blockDim.x + threadIdx.x;
    if (idx >= 16384) return;
    int n = idx >> 7, k = idx & 127;
    float v = wo[k * 128 + n];
    __nv_bfloat16 h = __float2bfloat16(v);
    g_Wbo[n * 128 + k] = h;
    g_Wbo[16384 + n * 128 + k] = __float2bfloat16(v - __bfloat162float(h));
}

// ---------------------------------------------------------------------------
// bf16 split-3 tensor-core GEMM, 256 threads (8 warps 2x4, warp tile 64x32),
// cp.async DOUBLE-BUFFERED B tiles.
// SMEM: A_hi 0..34816, A_lo ..69632, Bbuf0 ..139264, Bbuf1 ..208896, stats +1KB
// ---------------------------------------------------------------------------
static constexpr int HG_SMEM = 208896 + 1024;

__device__ __forceinline__ void prefetchB(char* sm, int bufOff,
                                          const __nv_bfloat16* Bg, int tid) {
    #pragma unroll
    for (int i = 0; i < 16; i++) {
        int f  = tid + i * 256;      // 0..4095 uint4s
        int hl = f >> 11;
        int g  = f & 2047;
        int r  = g >> 4;
        int ch = g & 15;
        const void* src = (const void*)(Bg + hl * 16384 + r * 128 + ch * 8);
        uint32_t dst = smem_u32(sm + bufOff + hl * 34816 + r * 272 + ch * 16);
        CP_ASYNC16(dst, src);
    }
    CP_COMMIT();
}

template<int NJT, bool STEADD, bool STATS, bool BIASF, bool QKVMAP>
__global__ void __launch_bounds__(256, 1)
hgemm_kernel(const float* __restrict__ A, const __nv_bfloat16* __restrict__ Bp,
             const float* __restrict__ bias, const float* __restrict__ steg,
             float* __restrict__ C, float* __restrict__ stats, int statsOff)
{
    constexpr int NC = NJT * 128;
    constexpr int A_LO = 34816;
    constexpr int B_BUF0 = 69632, B_BUF1 = 139264;
    constexpr int ST_OFF = 208896;

    extern __shared__ char sm[];
    const uint32_t sb = smem_u32(sm);

    const int tid  = threadIdx.x;
    const int lane = tid & 31;
    const int wid  = tid >> 5;
    const int wm   = wid >> 2;      // 0..1
    const int wn   = wid & 3;       // 0..3

    int m0, sterow0 = 0;
    if (QKVMAP) {
        int bx = blockIdx.x;
        int t = bx % 7, u = bx / 7;
        int nblk = u & 15, b = u >> 4;
        m0 = (b * 7 + t) * NN + nblk * 128;
        sterow0 = b * NN + nblk * 128;
    } else {
        m0 = blockIdx.x * 128;
    }

    // ---- kick off async prefetch of B tile 0, then load+split A (overlaps) ----
    prefetchB(sm, B_BUF0, Bp, tid);

    {
        const float* Ag = A + (size_t)m0 * 128;
        #pragma unroll
        for (int i = 0; i < 16; i++) {
            int f  = tid + i * 256;       // 0..4095 float4s
            int r  = f >> 5;
            int c4 = (f & 31) << 2;
            float4 v = *(const float4*)(Ag + (size_t)r * 128 + c4);
            __nv_bfloat16 hx = __float2bfloat16(v.x);
            __nv_bfloat16 hy = __float2bfloat16(v.y);
            __nv_bfloat16 hz = __float2bfloat16(v.z);
            __nv_bfloat16 hw = __float2bfloat16(v.w);
            __nv_bfloat162 hp0; hp0.x = hx; hp0.y = hy;
            __nv_bfloat162 hp1; hp1.x = hz; hp1.y = hw;
            uint2 hv; hv.x = *(uint32_t*)&hp0; hv.y = *(uint32_t*)&hp1;
            __nv_bfloat162 lp0, lp1;
            lp0.x = __float2bfloat16(v.x - __bfloat162float(hx));
            lp0.y = __float2bfloat16(v.y - __bfloat162float(hy));
            lp1.x = __float2bfloat16(v.z - __bfloat162float(hz));
            lp1.y = __float2bfloat16(v.w - __bfloat162float(hw));
            uint2 lv; lv.x = *(uint32_t*)&lp0; lv.y = *(uint32_t*)&lp1;
            *(uint2*)(sm + r * 272 + c4 * 2)        = hv;
            *(uint2*)(sm + A_LO + r * 272 + c4 * 2) = lv;
        }
    }

    const int gid = lane >> 2, tig = lane & 3;
    const uint32_t aBase = sb + (wm * 64 + (lane & 15)) * 272 + ((lane >> 4) & 1) * 16;
    const uint32_t bLane = (wn * 32 + (lane & 7) + ((lane >> 4) << 3)) * 272
                           + ((lane >> 3) & 1) * 16;

    #pragma unroll 1
    for (int jt = 0; jt < NJT; jt++) {
        const int curOff = (jt & 1) ? B_BUF1 : B_BUF0;

        // issue prefetch for next tile into the other buffer, then wait for current
        if (jt + 1 < NJT) {
            prefetchB(sm, (jt & 1) ? B_BUF0 : B_BUF1, Bp + (size_t)(jt + 1) * 2 * 16384, tid);
            CP_WAIT1();
        } else {
            CP_WAIT0();
        }
        if (STATS && tid < 128) {
            ((float*)(sm + ST_OFF))[tid] = 0.0f;
            ((float*)(sm + ST_OFF))[tid + 128] = 0.0f;
        }
        __syncthreads();   // B[jt] visible to all threads; stats zeroed; prev epilogue done

        const uint32_t bBase = sb + curOff + bLane;

        // ---- mainloop: K=128 in 8 steps of k16, 3 split terms ----
        float acc[4][4][4];
        #pragma unroll
        for (int i = 0; i < 4; i++)
            #pragma unroll
            for (int j = 0; j < 4; j++)
                #pragma unroll
                for (int q = 0; q < 4; q++) acc[i][j][q] = 0.0f;

        #pragma unroll
        for (int kb = 0; kb < 8; kb++) {
            const int kby = kb * 32;
            uint32_t ah[4][4], al[4][4], bh[2][4], bl[2][4];
            #pragma unroll
            for (int mf = 0; mf < 4; mf++) LDM4(ah[mf], aBase + mf * 4352 + kby);
            #pragma unroll
            for (int mf = 0; mf < 4; mf++) LDM4(al[mf], aBase + A_LO + mf * 4352 + kby);
            #pragma unroll
            for (int g2 = 0; g2 < 2; g2++) LDM4(bh[g2], bBase + g2 * 4352 + kby);
            #pragma unroll
            for (int g2 = 0; g2 < 2; g2++) LDM4(bl[g2], bBase + 34816 + g2 * 4352 + kby);

            #pragma unroll
            for (int mf = 0; mf < 4; mf++)
                #pragma unroll
                for (int ng = 0; ng < 4; ng++) {
                    int g = ng >> 1, o = (ng & 1) * 2;
                    MMA16(acc[mf][ng], ah[mf], bh[g][o], bh[g][o + 1]);
                }
            #pragma unroll
            for (int mf = 0; mf < 4; mf++)
                #pragma unroll
                for (int ng = 0; ng < 4; ng++) {
                    int g = ng >> 1, o = (ng & 1) * 2;
                    MMA16(acc[mf][ng], ah[mf], bl[g][o], bl[g][o + 1]);
                }
            #pragma unroll
            for (int mf = 0; mf < 4; mf++)
                #pragma unroll
                for (int ng = 0; ng < 4; ng++) {
                    int g = ng >> 1, o = (ng & 1) * 2;
                    MMA16(acc[mf][ng], al[mf], bh[g][o], bh[g][o + 1]);
                }
        }

        // ---- epilogue ----
        float csum[8], csq[8];
        #pragma unroll
        for (int i = 0; i < 8; i++) { csum[i] = 0.0f; csq[i] = 0.0f; }

        float2 bb[4];
        #pragma unroll
        for (int ng = 0; ng < 4; ng++) {
            if (BIASF) bb[ng] = *(const float2*)(bias + jt * 128 + wn * 32 + ng * 8 + tig * 2);
            else       bb[ng] = make_float2(0.0f, 0.0f);
        }

        #pragma unroll
        for (int mf = 0; mf < 4; mf++) {
            int mloc0 = wm * 64 + mf * 16 + gid;
            #pragma unroll
            for (int ng = 0; ng < 4; ng++) {
                int nloc = wn * 32 + ng * 8 + tig * 2;
                int jcol = jt * 128 + nloc;
                #pragma unroll
                for (int h = 0; h < 2; h++) {
                    int mloc = mloc0 + h * 8;
                    float v0 = acc[mf][ng][h * 2 + 0] + bb[ng].x;
                    float v1 = acc[mf][ng][h * 2 + 1] + bb[ng].y;
                    if (STEADD) {
                        float2 ss = *(const float2*)(steg + (size_t)(sterow0 + mloc) * 384 + jcol);
                        v0 += ss.x; v1 += ss.y;
                    }
                    *(float2*)(C + (size_t)(m0 + mloc) * NC + jcol) = make_float2(v0, v1);
                    if (STATS) {
                        csum[ng * 2 + 0] += v0; csq[ng * 2 + 0] += v0 * v0;
                        csum[ng * 2 + 1] += v1; csq[ng * 2 + 1] += v1 * v1;
                    }
                }
            }
        }

        if (STATS) {
            float* ssum = (float*)(sm + ST_OFF);
            float* ssq  = ssum + 128;
            #pragma unroll
            for (int ng = 0; ng < 4; ng++) {
                #pragma unroll
                for (int h2 = 0; h2 < 2; h2++) {
                    int nl = wn * 32 + ng * 8 + tig * 2 + h2;
                    atomicAdd(&ssum[nl], csum[ng * 2 + h2]);
                    atomicAdd(&ssq[nl],  csq[ng * 2 + h2]);
                }
            }
            __syncthreads();
            if (tid < 128) {
                atomicAdd(&stats[statsOff + jt * 128 + tid],       ssum[tid]);
                atomicAdd(&stats[512 + statsOff + jt * 128 + tid], ssq[tid]);
            }
        }
        __syncthreads();   // all reads of buf[jt] done before it is refilled (jt+2)
    }
}

// ---------------------------------------------------------------------------
// BN affine params
// ---------------------------------------------------------------------------
__global__ void bn_params_kernel(const float* __restrict__ stats, int off,
                                 const float* __restrict__ gamma, const float* __restrict__ beta,
                                 float* __restrict__ scale, float* __restrict__ shift,
                                 int outOff, float invM)
{
    int c = threadIdx.x;
    float s  = stats[off + c];
    float sq = stats[512 + off + c];
    float mu  = s * invM;
    float var = sq * invM - mu * mu;
    float rs  = rsqrtf(var + 1e-5f);
    float sc  = gamma[c] * rs;
    scale[outOff + c] = sc;
    shift[outOff + c] = beta[c] - mu * sc;
}

// ---------------------------------------------------------------------------
// Fused BN+GELU(q,k,v) + 16-head dim-8 attention over T=7, per (b,n)
// ---------------------------------------------------------------------------
__global__ void __launch_bounds__(128)
attn_kernel(const float* __restrict__ y, const float* __restrict__ scale,
            const float* __restrict__ shift, float* __restrict__ att_out)
{
    __shared__ float qkv[7][384];
    __shared__ float obuf[7][128];

    int bn  = blockIdx.x;
    int b   = bn >> 11;
    int n   = bn & (NN - 1);
    int tid = threadIdx.x;

    #pragma unroll
    for (int t = 0; t < 7; t++) {
        const float* row = y + (size_t)((b * 7 + t) * NN + n) * 384;
        #pragma unroll
        for (int it = 0; it < 3; it++) {
            int idx = tid + it * 128;
            float v = row[idx] * scale[idx] + shift[idx];
            qkv[t][idx] = gelu_f(v);
        }
    }
    __syncthreads();

    if (tid < 112) {
        int h = tid / 7;
        int t = tid - h * 7;
        int off = h * 8;
        float s[7], mx = -1e30f;
        #pragma unroll
        for (int j = 0; j < 7; j++) {
            float dsum = 0.0f;
            #pragma unroll
            for (int c = 0; c < 8; c++) dsum += qkv[t][off + c] * qkv[j][128 + off + c];
            s[j] = dsum * 0.25f;
            mx = fmaxf(mx, s[j]);
        }
        float ssum = 0.0f;
        #pragma unroll
        for (int j = 0; j < 7; j++) { s[j] = __expf(s[j] - mx); ssum += s[j]; }
        float inv = 1.0f / ssum;
        float o[8];
        #pragma unroll
        for (int c = 0; c < 8; c++) o[c] = 0.0f;
        #pragma unroll
        for (int j = 0; j < 7; j++) {
            float p = s[j] * inv;
            #pragma unroll
            for (int c = 0; c < 8; c++) o[c] += p * qkv[j][256 + off + c];
        }
        #pragma unroll
        for (int c = 0; c < 8; c++) obuf[t][off + c] = o[c];
    }
    __syncthreads();

    #pragma unroll
    for (int t = 0; t < 7; t++)
        att_out[(size_t)((b * 7 + t) * NN + n) * 128 + tid] = obuf[t][tid];
}

// ---------------------------------------------------------------------------
// Final: BN+GELU(o) fused with Linear(7->1) over time
// ---------------------------------------------------------------------------
__global__ void final_kernel(const float* __restrict__ opre, const float* __restrict__ lw,
                             const float* __restrict__ lb, const float* __restrict__ scale,
                             const float* __restrict__ shift, float* __restrict__ out)
{
    int idx = blockIdx.x * blockDim.x + threadIdx.x;
    if (idx >= BB * NN * DD) return;
    int d = idx & 127;
    int n = (idx >> 7) & (NN - 1);
    int b = idx >> 18;
    float sc = scale[d], sh = shift[d];
    float acc = lb[0];
    #pragma unroll
    for (int t = 0; t < 7; t++) {
        float v = opre[(size_t)((b * 7 + t) * NN + n) * 128 + d];
        acc += gelu_f(v * sc + sh) * lw[t];
    }
    out[idx] = acc;
}

// ---------------------------------------------------------------------------
// Launcher
// ---------------------------------------------------------------------------
extern "C" void kernel_launch(void* const* d_in, const int* in_sizes, int n_in,
                              void* d_out, int out_size)
{
    const float* X   = (const float*)d_in[0];
    const float* STE = (const float*)d_in[1];
    const float* wq  = (const float*)d_in[2];
    const float* bq  = (const float*)d_in[3];
    const float* gq  = (const float*)d_in[4];
    const float* btq = (const float*)d_in[5];
    const float* wk  = (const float*)d_in[6];
    const float* bk  = (const float*)d_in[7];
    const float* gk  = (const float*)d_in[8];
    const float* btk = (const float*)d_in[9];
    const float* wv  = (const float*)d_in[10];
    const float* bv  = (const float*)d_in[11];
    const float* gv  = (const float*)d_in[12];
    const float* btv = (const float*)d_in[13];
    const float* wo  = (const float*)d_in[14];
    const float* bo  = (const float*)d_in[15];
    const float* go  = (const float*)d_in[16];
    const float* bto = (const float*)d_in[17];
    const float* lw  = (const float*)d_in[18];
    const float* lb  = (const float*)d_in[19];
    float* out = (float*)d_out;

    float *pBias, *pSte, *pY, *pAtt, *pOpre, *pStats, *pScale, *pShift;
    __nv_bfloat16 *pWb1, *pWb2, *pWbo;
    cudaGetSymbolAddress((void**)&pWb1,   g_Wb1);
    cudaGetSymbolAddress((void**)&pWb2,   g_Wb2);
    cudaGetSymbolAddress((void**)&pWbo,   g_Wbo);
    cudaGetSymbolAddress((void**)&pBias,  g_bias);
    cudaGetSymbolAddress((void**)&pSte,   g_ste);
    cudaGetSymbolAddress((void**)&pY,     g_y);
    cudaGetSymbolAddress((void**)&pAtt,   g_attout);
    cudaGetSymbolAddress((void**)&pOpre,  g_opre);
    cudaGetSymbolAddress((void**)&pStats, g_stats);
    cudaGetSymbolAddress((void**)&pScale, g_bnscale);
    cudaGetSymbolAddress((void**)&pShift, g_bnshift);

    cudaFuncSetAttribute((const void*)hgemm_kernel<3, false, false, true,  false>,
                         cudaFuncAttributeMaxDynamicSharedMemorySize, HG_SMEM);
    cudaFuncSetAttribute((const void*)hgemm_kernel<3, true,  true,  false, true>,
                         cudaFuncAttributeMaxDynamicSharedMemorySize, HG_SMEM);
    cudaFuncSetAttribute((const void*)hgemm_kernel<1, false, true,  true,  false>,
                         cudaFuncAttributeMaxDynamicSharedMemorySize, HG_SMEM);

    const float invM = 1.0f / (float)M1;

    zero_stats_kernel<<<1, 1024>>>();
    pack_qkv_kernel<<<(3 * 128 * 128 + 255) / 256, 256>>>(wq, bq, wk, bk, wv, bv);
    pack_wo_kernel<<<64, 256>>>(wo);

    // STE part of QKV FC: [32768,128] @ W2 + bias -> g_ste
    hgemm_kernel<3, false, false, true, false><<<M0 / 128, 256, HG_SMEM>>>(
        STE, pWb2, pBias, nullptr, pSte, nullptr, 0);

    // X part + STE add + stats: [229376,128] @ W1 -> g_y
    hgemm_kernel<3, true, true, false, true><<<M1 / 128, 256, HG_SMEM>>>(
        X, pWb1, nullptr, pSte, pY, pStats, 0);

    bn_params_kernel<<<1, 128>>>(pStats,   0, gq, btq, pScale, pShift,   0, invM);
    bn_params_kernel<<<1, 128>>>(pStats, 128, gk, btk, pScale, pShift, 128, invM);
    bn_params_kernel<<<1, 128>>>(pStats, 256, gv, btv, pScale, pShift, 256, invM);

    attn_kernel<<<M0, 128>>>(pY, pScale, pShift, pAtt);

    // O FC: [229376,128] @ wo + bias + stats -> g_opre
    hgemm_kernel<1, false, true, true, false><<<M1 / 128, 256, HG_SMEM>>>(
        pAtt, pWbo, bo, nullptr, pOpre, pStats, 384);

    bn_params_kernel<<<1, 128>>>(pStats, 384, go, bto, pScale, pShift, 384, invM);

    final_kernel<<<(BB * NN * DD + 255) / 256, 256>>>(pOpre, lw, lb, pScale + 384, pShift + 384, out);
}

// round 9
// speedup vs baseline: 1.0871x; 1.0228x over previous
#include <cuda_runtime.h>
#include <cuda_bf16.h>
#include <math.h>
#include <cstdint>

// ---------------------------------------------------------------------------
// Problem constants
// ---------------------------------------------------------------------------
#define BB 16
#define TT 7
#define NN 2048
#define DD 128
#define M1 (BB*TT*NN)   /* 229376 */
#define M0 (BB*NN)      /* 32768  */

// ---------------------------------------------------------------------------
// mma.sync / ldmatrix / cp.async helpers (generic sm_80+, works on compute_100)
// ---------------------------------------------------------------------------
__device__ __forceinline__ uint32_t smem_u32(const void* p) {
    uint32_t a;
    asm("{ .reg .u64 t; cvta.to.shared.u64 t, %1; cvt.u32.u64 %0, t; }" : "=r"(a) : "l"(p));
    return a;
}

#define LDM4(r, a) \
    asm volatile("ldmatrix.sync.aligned.m8n8.x4.shared.b16 {%0,%1,%2,%3}, [%4];" \
        : "=r"((r)[0]), "=r"((r)[1]), "=r"((r)[2]), "=r"((r)[3]) : "r"(a))

#define MMA16(c, a, b0_, b1_) \
    asm volatile("mma.sync.aligned.m16n8k16.row.col.f32.bf16.bf16.f32 " \
        "{%0,%1,%2,%3},{%4,%5,%6,%7},{%8,%9},{%0,%1,%2,%3};" \
        : "+f"((c)[0]), "+f"((c)[1]), "+f"((c)[2]), "+f"((c)[3]) \
        : "r"((a)[0]), "r"((a)[1]), "r"((a)[2]), "r"((a)[3]), "r"(b0_), "r"(b1_))

#define CP_ASYNC16(dst, src) \
    asm volatile("cp.async.ca.shared.global [%0], [%1], 16;" :: "r"(dst), "l"(src) : "memory")
#define CP_COMMIT() asm volatile("cp.async.commit_group;" ::: "memory")
#define CP_WAIT0()  asm volatile("cp.async.wait_group 0;" ::: "memory")

// ---------------------------------------------------------------------------
// Device scratch
// ---------------------------------------------------------------------------
__device__ __nv_bfloat16 g_Wb1[6 * 16384];   // QKV X-part: [jt*2+hl][n][k]
__device__ __nv_bfloat16 g_Wb2[6 * 16384];   // QKV STE-part
__device__ __nv_bfloat16 g_Wbo[2 * 16384];   // O weights
__device__ float g_bias[384];
__device__ float g_ste[(size_t)M0 * 384];
__device__ float g_y[(size_t)M1 * 384];
__device__ float g_attout[(size_t)M1 * 128];
__device__ float g_opre[(size_t)M1 * 128];
__device__ float g_stats[1024];
__device__ float g_bnscale[512];
__device__ float g_bnshift[512];

__device__ __forceinline__ float gelu_f(float x) {
    return 0.5f * x * (1.0f + erff(x * 0.70710678118654752f));
}

// ---------------------------------------------------------------------------
// Utility kernels
// ---------------------------------------------------------------------------
__global__ void zero_stats_kernel() { g_stats[threadIdx.x] = 0.0f; }

__global__ void pack_qkv_kernel(const float* __restrict__ wq, const float* __restrict__ bq,
                                const float* __restrict__ wk, const float* __restrict__ bk,
                                const float* __restrict__ wv, const float* __restrict__ bv) {
    int idx = blockIdx.x * blockDim.x + threadIdx.x;
    if (idx >= 3 * 128 * 128) return;
    int jt = idx >> 14;
    int n  = (idx >> 7) & 127;
    int k  = idx & 127;
    const float* w = (jt == 0) ? wq : (jt == 1) ? wk : wv;
    float v1 = w[k * 128 + n];
    float v2 = w[(k + 128) * 128 + n];
    __nv_bfloat16 h1 = __float2bfloat16(v1);
    __nv_bfloat16 h2 = __float2bfloat16(v2);
    g_Wb1[(jt * 2 + 0) * 16384 + n * 128 + k] = h1;
    g_Wb1[(jt * 2 + 1) * 16384 + n * 128 + k] = __float2bfloat16(v1 - __bfloat162float(h1));
    g_Wb2[(jt * 2 + 0) * 16384 + n * 128 + k] = h2;
    g_Wb2[(jt * 2 + 1) * 16384 + n * 128 + k] = __float2bfloat16(v2 - __bfloat162float(h2));
    if (k == 0) {
        const float* bb = (jt == 0) ? bq : (jt == 1) ? bk : bv;
        g_bias[jt * 128 + n] = bb[n];
    }
}

__global__ void pack_wo_kernel(const float* __restrict__ wo) {
    int idx = blockIdx.x * blockDim.x + threadIdx.x;
    if (idx >= 16384) return;
    int n = idx >> 7, k = idx & 127;
    float v = wo[k * 128 + n];
    __nv_bfloat16 h = __float2bfloat16(v);
    g_Wbo[n * 128 + k] = h;
    g_Wbo[16384 + n * 128 + k] = __float2bfloat16(v - __bfloat162float(h));
}

// ---------------------------------------------------------------------------
// bf16 split-3 tensor-core GEMM, 256 threads (8 warps 2x4, warp tile 64x32),
// CTA M-tile = 256 rows (two 128-row halves per jt share one B tile).
// SMEM: A_hi 0..69632, A_lo ..139264, B(hi+lo) ..208896, stats +1KB = 209,920
// ---------------------------------------------------------------------------
static constexpr int HG_SMEM = 208896 + 1024;

__device__ __forceinline__ void prefetchB(char* sm, const __nv_bfloat16* Bg, int tid) {
    constexpr int B_OFF = 139264;
    #pragma unroll
    for (int i = 0; i < 16; i++) {
        int f  = tid + i * 256;      // 0..4095 uint4s
        int hl = f >> 11;
        int g  = f & 2047;
        int r  = g >> 4;
        int ch = g & 15;
        const void* src = (const void*)(Bg + hl * 16384 + r * 128 + ch * 8);
        uint32_t dst = smem_u32(sm + B_OFF + hl * 34816 + r * 272 + ch * 16);
        CP_ASYNC16(dst, src);
    }
    CP_COMMIT();
}

template<int NJT, bool STEADD, bool STATS, bool BIASF, bool QKVMAP>
__global__ void __launch_bounds__(256, 1)
hgemm_kernel(const float* __restrict__ A, const __nv_bfloat16* __restrict__ Bp,
             const float* __restrict__ bias, const float* __restrict__ steg,
             float* __restrict__ C, float* __restrict__ stats, int statsOff)
{
    constexpr int NC = NJT * 128;
    constexpr int A_LO = 69632;
    constexpr int B_OFF = 139264;
    constexpr int ST_OFF = 208896;

    extern __shared__ char sm[];
    const uint32_t sb = smem_u32(sm);

    const int tid  = threadIdx.x;
    const int lane = tid & 31;
    const int wid  = tid >> 5;
    const int wm   = wid >> 2;      // 0..1
    const int wn   = wid & 3;       // 0..3

    int m0, sterow0 = 0;
    if (QKVMAP) {
        int bx = blockIdx.x;
        int t = bx % 7, u = bx / 7;
        int nblk = u & 7, b = u >> 3;
        m0 = (b * 7 + t) * NN + nblk * 256;
        sterow0 = b * NN + nblk * 256;
    } else {
        m0 = blockIdx.x * 256;
    }

    // ---- kick off async prefetch of B tile 0, then load+split A (overlaps) ----
    prefetchB(sm, Bp, tid);

    {
        const float* Ag = A + (size_t)m0 * 128;
        #pragma unroll
        for (int i = 0; i < 32; i++) {
            int f  = tid + i * 256;       // 0..8191 float4s (256 rows x 32)
            int r  = f >> 5;
            int c4 = (f & 31) << 2;
            float4 v = *(const float4*)(Ag + (size_t)r * 128 + c4);
            __nv_bfloat16 hx = __float2bfloat16(v.x);
            __nv_bfloat16 hy = __float2bfloat16(v.y);
            __nv_bfloat16 hz = __float2bfloat16(v.z);
            __nv_bfloat16 hw = __float2bfloat16(v.w);
            __nv_bfloat162 hp0; hp0.x = hx; hp0.y = hy;
            __nv_bfloat162 hp1; hp1.x = hz; hp1.y = hw;
            uint2 hv; hv.x = *(uint32_t*)&hp0; hv.y = *(uint32_t*)&hp1;
            __nv_bfloat162 lp0, lp1;
            lp0.x = __float2bfloat16(v.x - __bfloat162float(hx));
            lp0.y = __float2bfloat16(v.y - __bfloat162float(hy));
            lp1.x = __float2bfloat16(v.z - __bfloat162float(hz));
            lp1.y = __float2bfloat16(v.w - __bfloat162float(hw));
            uint2 lv; lv.x = *(uint32_t*)&lp0; lv.y = *(uint32_t*)&lp1;
            *(uint2*)(sm + r * 272 + c4 * 2)        = hv;
            *(uint2*)(sm + A_LO + r * 272 + c4 * 2) = lv;
        }
    }

    const int gid = lane >> 2, tig = lane & 3;
    const uint32_t bBase = sb + B_OFF + (wn * 32 + (lane & 7) + ((lane >> 4) << 3)) * 272
                           + ((lane >> 3) & 1) * 16;

    #pragma unroll 1
    for (int jt = 0; jt < NJT; jt++) {
        CP_WAIT0();
        if (STATS && tid < 128) {
            ((float*)(sm + ST_OFF))[tid] = 0.0f;
            ((float*)(sm + ST_OFF))[tid + 128] = 0.0f;
        }
        __syncthreads();   // B[jt] visible; stats zeroed; prev jt done

        float2 bb[4];
        #pragma unroll
        for (int ng = 0; ng < 4; ng++) {
            if (BIASF) bb[ng] = *(const float2*)(bias + jt * 128 + wn * 32 + ng * 8 + tig * 2);
            else       bb[ng] = make_float2(0.0f, 0.0f);
        }

        #pragma unroll 1
        for (int mh = 0; mh < 2; mh++) {
            const uint32_t aBase = sb + (mh * 128 + wm * 64 + (lane & 15)) * 272
                                   + ((lane >> 4) & 1) * 16;

            // ---- mainloop: K=128 in 8 steps of k16, 3 split terms ----
            float acc[4][4][4];
            #pragma unroll
            for (int i = 0; i < 4; i++)
                #pragma unroll
                for (int j = 0; j < 4; j++)
                    #pragma unroll
                    for (int q = 0; q < 4; q++) acc[i][j][q] = 0.0f;

            #pragma unroll
            for (int kb = 0; kb < 8; kb++) {
                const int kby = kb * 32;
                uint32_t ah[4][4], al[4][4], bh[2][4], bl[2][4];
                #pragma unroll
                for (int mf = 0; mf < 4; mf++) LDM4(ah[mf], aBase + mf * 4352 + kby);
                #pragma unroll
                for (int mf = 0; mf < 4; mf++) LDM4(al[mf], aBase + A_LO + mf * 4352 + kby);
                #pragma unroll
                for (int g2 = 0; g2 < 2; g2++) LDM4(bh[g2], bBase + g2 * 4352 + kby);
                #pragma unroll
                for (int g2 = 0; g2 < 2; g2++) LDM4(bl[g2], bBase + 34816 + g2 * 4352 + kby);

                #pragma unroll
                for (int mf = 0; mf < 4; mf++)
                    #pragma unroll
                    for (int ng = 0; ng < 4; ng++) {
                        int g = ng >> 1, o = (ng & 1) * 2;
                        MMA16(acc[mf][ng], ah[mf], bh[g][o], bh[g][o + 1]);
                    }
                #pragma unroll
                for (int mf = 0; mf < 4; mf++)
                    #pragma unroll
                    for (int ng = 0; ng < 4; ng++) {
                        int g = ng >> 1, o = (ng & 1) * 2;
                        MMA16(acc[mf][ng], ah[mf], bl[g][o], bl[g][o + 1]);
                    }
                #pragma unroll
                for (int mf = 0; mf < 4; mf++)
                    #pragma unroll
                    for (int ng = 0; ng < 4; ng++) {
                        int g = ng >> 1, o = (ng & 1) * 2;
                        MMA16(acc[mf][ng], al[mf], bh[g][o], bh[g][o + 1]);
                    }
            }

            // ---- epilogue for this half ----
            float csum[8], csq[8];
            #pragma unroll
            for (int i = 0; i < 8; i++) { csum[i] = 0.0f; csq[i] = 0.0f; }

            #pragma unroll
            for (int mf = 0; mf < 4; mf++) {
                int mloc0 = mh * 128 + wm * 64 + mf * 16 + gid;
                #pragma unroll
                for (int ng = 0; ng < 4; ng++) {
                    int nloc = wn * 32 + ng * 8 + tig * 2;
                    int jcol = jt * 128 + nloc;
                    #pragma unroll
                    for (int h = 0; h < 2; h++) {
                        int mloc = mloc0 + h * 8;
                        float v0 = acc[mf][ng][h * 2 + 0] + bb[ng].x;
                        float v1 = acc[mf][ng][h * 2 + 1] + bb[ng].y;
                        if (STEADD) {
                            float2 ss = *(const float2*)(steg + (size_t)(sterow0 + mloc) * 384 + jcol);
                            v0 += ss.x; v1 += ss.y;
                        }
                        *(float2*)(C + (size_t)(m0 + mloc) * NC + jcol) = make_float2(v0, v1);
                        if (STATS) {
                            csum[ng * 2 + 0] += v0; csq[ng * 2 + 0] += v0 * v0;
                            csum[ng * 2 + 1] += v1; csq[ng * 2 + 1] += v1 * v1;
                        }
                    }
                }
            }

            if (STATS) {
                float* ssum = (float*)(sm + ST_OFF);
                float* ssq  = ssum + 128;
                #pragma unroll
                for (int ng = 0; ng < 4; ng++) {
                    #pragma unroll
                    for (int h2 = 0; h2 < 2; h2++) {
                        int nl = wn * 32 + ng * 8 + tig * 2 + h2;
                        atomicAdd(&ssum[nl], csum[ng * 2 + h2]);
                        atomicAdd(&ssq[nl],  csq[ng * 2 + h2]);
                    }
                }
            }
        }

        __syncthreads();   // both halves done: B reads + smem stats complete
        if (STATS && tid < 128) {
            atomicAdd(&stats[statsOff + jt * 128 + tid],       ((float*)(sm + ST_OFF))[tid]);
            atomicAdd(&stats[512 + statsOff + jt * 128 + tid], ((float*)(sm + ST_OFF))[tid + 128]);
        }
        if (jt + 1 < NJT)
            prefetchB(sm, Bp + (size_t)(jt + 1) * 2 * 16384, tid);  // safe: post-sync
    }
}

// ---------------------------------------------------------------------------
// BN affine params
// ---------------------------------------------------------------------------
__global__ void bn_params_kernel(const float* __restrict__ stats, int off,
                                 const float* __restrict__ gamma, const float* __restrict__ beta,
                                 float* __restrict__ scale, float* __restrict__ shift,
                                 int outOff, float invM)
{
    int c = threadIdx.x;
    float s  = stats[off + c];
    float sq = stats[512 + off + c];
    float mu  = s * invM;
    float var = sq * invM - mu * mu;
    float rs  = rsqrtf(var + 1e-5f);
    float sc  = gamma[c] * rs;
    scale[outOff + c] = sc;
    shift[outOff + c] = beta[c] - mu * sc;
}

// ---------------------------------------------------------------------------
// Fused BN+GELU(q,k,v) + 16-head dim-8 attention over T=7, per (b,n)
// ---------------------------------------------------------------------------
__global__ void __launch_bounds__(128)
attn_kernel(const float* __restrict__ y, const float* __restrict__ scale,
            const float* __restrict__ shift, float* __restrict__ att_out)
{
    __shared__ float qkv[7][384];
    __shared__ float obuf[7][128];

    int bn  = blockIdx.x;
    int b   = bn >> 11;
    int n   = bn & (NN - 1);
    int tid = threadIdx.x;

    #pragma unroll
    for (int t = 0; t < 7; t++) {
        const float* row = y + (size_t)((b * 7 + t) * NN + n) * 384;
        #pragma unroll
        for (int it = 0; it < 3; it++) {
            int idx = tid + it * 128;
            float v = row[idx] * scale[idx] + shift[idx];
            qkv[t][idx] = gelu_f(v);
        }
    }
    __syncthreads();

    if (tid < 112) {
        int h = tid / 7;
        int t = tid - h * 7;
        int off = h * 8;
        float s[7], mx = -1e30f;
        #pragma unroll
        for (int j = 0; j < 7; j++) {
            float dsum = 0.0f;
            #pragma unroll
            for (int c = 0; c < 8; c++) dsum += qkv[t][off + c] * qkv[j][128 + off + c];
            s[j] = dsum * 0.25f;
            mx = fmaxf(mx, s[j]);
        }
        float ssum = 0.0f;
        #pragma unroll
        for (int j = 0; j < 7; j++) { s[j] = __expf(s[j] - mx); ssum += s[j]; }
        float inv = 1.0f / ssum;
        float o[8];
        #pragma unroll
        for (int c = 0; c < 8; c++) o[c] = 0.0f;
        #pragma unroll
        for (int j = 0; j < 7; j++) {
            float p = s[j] * inv;
            #pragma unroll
            for (int c = 0; c < 8; c++) o[c] += p * qkv[j][256 + off + c];
        }
        #pragma unroll
        for (int c = 0; c < 8; c++) obuf[t][off + c] = o[c];
    }
    __syncthreads();

    #pragma unroll
    for (int t = 0; t < 7; t++)
        att_out[(size_t)((b * 7 + t) * NN + n) * 128 + tid] = obuf[t][tid];
}

// ---------------------------------------------------------------------------
// Final: BN+GELU(o) fused with Linear(7->1) over time
// ---------------------------------------------------------------------------
__global__ void final_kernel(const float* __restrict__ opre, const float* __restrict__ lw,
                             const float* __restrict__ lb, const float* __restrict__ scale,
                             const float* __restrict__ shift, float* __restrict__ out)
{
    int idx = blockIdx.x * blockDim.x + threadIdx.x;
    if (idx >= BB * NN * DD) return;
    int d = idx & 127;
    int n = (idx >> 7) & (NN - 1);
    int b = idx >> 18;
    float sc = scale[d], sh = shift[d];
    float acc = lb[0];
    #pragma unroll
    for (int t = 0; t < 7; t++) {
        float v = opre[(size_t)((b * 7 + t) * NN + n) * 128 + d];
        acc += gelu_f(v * sc + sh) * lw[t];
    }
    out[idx] = acc;
}

// ---------------------------------------------------------------------------
// Launcher
// ---------------------------------------------------------------------------
extern "C" void kernel_launch(void* const* d_in, const int* in_sizes, int n_in,
                              void* d_out, int out_size)
{
    const float* X   = (const float*)d_in[0];
    const float* STE = (const float*)d_in[1];
    const float* wq  = (const float*)d_in[2];
    const float* bq  = (const float*)d_in[3];
    const float* gq  = (const float*)d_in[4];
    const float* btq = (const float*)d_in[5];
    const float* wk  = (const float*)d_in[6];
    const float* bk  = (const float*)d_in[7];
    const float* gk  = (const float*)d_in[8];
    const float* btk = (const float*)d_in[9];
    const float* wv  = (const float*)d_in[10];
    const float* bv  = (const float*)d_in[11];
    const float* gv  = (const float*)d_in[12];
    const float* btv = (const float*)d_in[13];
    const float* wo  = (const float*)d_in[14];
    const float* bo  = (const float*)d_in[15];
    const float* go  = (const float*)d_in[16];
    const float* bto = (const float*)d_in[17];
    const float* lw  = (const float*)d_in[18];
    const float* lb  = (const float*)d_in[19];
    float* out = (float*)d_out;

    float *pBias, *pSte, *pY, *pAtt, *pOpre, *pStats, *pScale, *pShift;
    __nv_bfloat16 *pWb1, *pWb2, *pWbo;
    cudaGetSymbolAddress((void**)&pWb1,   g_Wb1);
    cudaGetSymbolAddress((void**)&pWb2,   g_Wb2);
    cudaGetSymbolAddress((void**)&pWbo,   g_Wbo);
    cudaGetSymbolAddress((void**)&pBias,  g_bias);
    cudaGetSymbolAddress((void**)&pSte,   g_ste);
    cudaGetSymbolAddress((void**)&pY,     g_y);
    cudaGetSymbolAddress((void**)&pAtt,   g_attout);
    cudaGetSymbolAddress((void**)&pOpre,  g_opre);
    cudaGetSymbolAddress((void**)&pStats, g_stats);
    cudaGetSymbolAddress((void**)&pScale, g_bnscale);
    cudaGetSymbolAddress((void**)&pShift, g_bnshift);

    cudaFuncSetAttribute((const void*)hgemm_kernel<3, false, false, true,  false>,
                         cudaFuncAttributeMaxDynamicSharedMemorySize, HG_SMEM);
    cudaFuncSetAttribute((const void*)hgemm_kernel<3, true,  true,  false, true>,
                         cudaFuncAttributeMaxDynamicSharedMemorySize, HG_SMEM);
    cudaFuncSetAttribute((const void*)hgemm_kernel<1, false, true,  true,  false>,
                         cudaFuncAttributeMaxDynamicSharedMemorySize, HG_SMEM);

    const float invM = 1.0f / (float)M1;

    zero_stats_kernel<<<1, 1024>>>();
    pack_qkv_kernel<<<(3 * 128 * 128 + 255) / 256, 256>>>(wq, bq, wk, bk, wv, bv);
    pack_wo_kernel<<<64, 256>>>(wo);

    // STE part of QKV FC: [32768,128] @ W2 + bias -> g_ste
    hgemm_kernel<3, false, false, true, false><<<M0 / 256, 256, HG_SMEM>>>(
        STE, pWb2, pBias, nullptr, pSte, nullptr, 0);

    // X part + STE add + stats: [229376,128] @ W1 -> g_y
    hgemm_kernel<3, true, true, false, true><<<M1 / 256, 256, HG_SMEM>>>(
        X, pWb1, nullptr, pSte, pY, pStats, 0);

    bn_params_kernel<<<1, 128>>>(pStats,   0, gq, btq, pScale, pShift,   0, invM);
    bn_params_kernel<<<1, 128>>>(pStats, 128, gk, btk, pScale, pShift, 128, invM);
    bn_params_kernel<<<1, 128>>>(pStats, 256, gv, btv, pScale, pShift, 256, invM);

    attn_kernel<<<M0, 128>>>(pY, pScale, pShift, pAtt);

    // O FC: [229376,128] @ wo + bias + stats -> g_opre
    hgemm_kernel<1, false, true, true, false><<<M1 / 256, 256, HG_SMEM>>>(
        pAtt, pWbo, bo, nullptr, pOpre, pStats, 384);

    bn_params_kernel<<<1, 128>>>(pStats, 384, go, bto, pScale, pShift, 384, invM);

    final_kernel<<<(BB * NN * DD + 255) / 256, 256>>>(pOpre, lw, lb, pScale + 384, pShift + 384, out);
}